// round 16
// baseline (speedup 1.0000x reference)
#include <cuda_runtime.h>
#include <cuda_fp16.h>
#include <cstdint>

// ---------------- problem constants ----------------
#define E_      32768
#define N0_     (15 * E_)
#define NTILES_ 2048                  // 262144 MLP rows / 128
#define NE_OLD_ 1114112
#define NE_NEW_ 2097152
#define NE_TOT_ (NE_OLD_ + NE_NEW_)
#define NNODES_ (31 * E_)

#define EI_OFF_ ((size_t)NNODES_ * 64)
#define EA_OFF_ (EI_OFF_ + 2ull * NE_TOT_)
#define EV_OFF_ (EA_OFF_ + (size_t)NE_TOT_)

// per-tile aux chunks (exact divisions by 2048)
#define XC_PER_TILE 3840              // uint4 of x-copy per MLP tile
#define OE_PER_TILE 544               // old edges per tile
#define NEDGE_PER_TILE 1024           // new edges per tile
#define EVT_PER_TILE 496              // events per tile

// old-edge block tables: block b (= i>>16, b<17) -> (l, p, d)
__device__ __constant__ unsigned char OE_L[17] = {1, 2,2,2,2, 3,3,3,3,3,3,3,3,3,3,3,3};
__device__ __constant__ unsigned char OE_P[17] = {0, 0,0,1,1, 0,0,0,1,1,1,2,2,2,3,3,3};
__device__ __constant__ unsigned char OE_D[17] = {1, 1,2,1,2, 1,2,3,1,2,3,1,2,3,1,2,3};

// ---------------- PTX helpers (base ISA only) ----------------
__device__ __forceinline__ uint32_t smem_u32(const void* p) {
    uint32_t a;
    asm("{ .reg .u64 t; cvta.to.shared.u64 t, %1; cvt.u32.u64 %0, t; }" : "=r"(a) : "l"(p));
    return a;
}

#define PREF_L2(p)      asm volatile("prefetch.global.L2 [%0];" :: "l"(p))

#define LDSM4(r0, r1, r2, r3, a)                                                   \
    asm volatile("ldmatrix.sync.aligned.m8n8.x4.shared.b16 {%0,%1,%2,%3}, [%4];"   \
        : "=r"(r0), "=r"(r1), "=r"(r2), "=r"(r3) : "r"(a))

#define MMA_F16(d, a0, a1, a2, a3, b0, b1)                                         \
    asm volatile("mma.sync.aligned.m16n8k16.row.col.f32.f16.f16.f32 "              \
        "{%0,%1,%2,%3}, {%4,%5,%6,%7}, {%8,%9}, {%0,%1,%2,%3};"                    \
        : "+f"((d)[0]), "+f"((d)[1]), "+f"((d)[2]), "+f"((d)[3])                   \
        : "r"(a0), "r"(a1), "r"(a2), "r"(a3), "r"(b0), "r"(b1))

__device__ __forceinline__ uint32_t h2u(__half2 h) {
    return *reinterpret_cast<uint32_t*>(&h);
}

// ---------------- device scratch / coordination ----------------
__device__ __align__(16) unsigned char glGB[(size_t)E_ * 512];  // GB = G@W1bot + b1, fp16 [E][256]
__device__ int g_ticket;        // tile work queue
__device__ int g_gbwork;        // GB block work queue
__device__ int g_done;          // completion counter (for reset)
__device__ int g_gbflag[256];   // GB block ready flags

// ---------------- smem layout (bytes) ----------------
// phase 0 reuses:  SM_A = g tile (18432), SM_W1 = W1bot image (36864),
//                  SM_W2 = GB staging 128x528 (67584 <= 69632)
#define SM_A    0                         // 18432
#define SM_W1   18432                     // 36864
#define SM_W2   55296                     // 69632
#define SM_H    124928                    // 34816
#define SM_B2   159744                    // 512
#define SM_SZ   160256

__device__ __forceinline__ void build_A(unsigned char* Abuf, int m0,
                                        const float* __restrict__ x, int t)
{
    const int r = t >> 2, q = t & 3;
    const float4* src = (const float4*)(x + ((size_t)(7 * E_) + (size_t)(m0 + r)) * 64 + 16 * q);
    unsigned char* Ap = Abuf + (size_t)r * 144 + (size_t)q * 32;
    #pragma unroll
    for (int i = 0; i < 4; i++) {
        float4 v = src[i];
        *(uint2*)(Ap + i * 8) = make_uint2(h2u(__float22half2_rn(make_float2(v.x, v.y))),
                                           h2u(__float22half2_rn(make_float2(v.z, v.w))));
    }
}

#define XCOPY_ISSUE(k)                                                              \
    do {                                                                            \
        int _i0 = t + (2 * (k)) * 512, _i1 = t + (2 * (k) + 1) * 512;               \
        if (_i0 < XC_PER_TILE) cr0 = __ldcs(xs4 + xb + _i0);                        \
        if (_i1 < XC_PER_TILE) cr1 = __ldcs(xs4 + xb + _i1);                        \
    } while (0)

#define XCOPY_CONSUME(k)                                                            \
    do {                                                                            \
        int _i0 = t + (2 * (k)) * 512, _i1 = t + (2 * (k) + 1) * 512;               \
        if (_i0 < XC_PER_TILE) __stcs(od4 + xb + _i0, cr0);                         \
        if (_i1 < XC_PER_TILE) __stcs(od4 + xb + _i1, cr1);                         \
    } while (0)

// ============================================================================
// fused persistent kernel: GB production (work-stealing) + MLP tile loop
// ============================================================================
__global__ void __launch_bounds__(512, 1)
fused_kernel(const float* __restrict__ x, const float* __restrict__ g,
             const float* __restrict__ W1, const float* __restrict__ b1,
             const float* __restrict__ W2, const float* __restrict__ b2,
             float* __restrict__ out)
{
    extern __shared__ __align__(128) unsigned char sm[];
    __shared__ int s_tile[2];
    __shared__ int s_blk;

    const int t = threadIdx.x;
    const int wid = t >> 5, l = t & 31;
    const int mg = wid & 7;
    const int ng = wid >> 3;
    const uint32_t sb = smem_u32(sm);

    const uint32_t off144 = (uint32_t)(l & 15) * 144u + (uint32_t)((l >> 4) << 4);
    const uint32_t off272 = (uint32_t)(l & 15) * 272u + (uint32_t)((l >> 4) << 4);
    const int hRow = l >> 2;
    const int hCol2 = (l & 3) << 1;

    // ================= phase 0: GB production (work-stealing) =================
    // W1 bottom (k 64..127) -> SM_W1 as [nh][128n][144B]
    for (int i = t; i < 16384; i += 512) {
        int kk = i >> 8, n = i & 255;
        uint32_t off = (uint32_t)(n >> 7) * 18432u + (uint32_t)(n & 127) * 144u + (uint32_t)kk * 2u;
        *(__half*)(sm + SM_W1 + off) = __float2half(W1[(64 + kk) * 256 + n]);
    }
    __syncthreads();

    while (true) {
        if (t == 0) s_blk = atomicAdd(&g_gbwork, 1);
        __syncthreads();
        const int b = s_blk;
        if (b >= 256) break;

        // g tile rows [128b, 128b+128) -> SM_A (padded 144B rows)
        {
            const int r = t >> 2, q = t & 3;
            const float4* src = (const float4*)(g + ((size_t)(b * 128 + r)) * 64 + 16 * q);
            unsigned char* Ap = sm + SM_A + (size_t)r * 144 + (size_t)q * 32;
            #pragma unroll
            for (int i = 0; i < 4; i++) {
                float4 v = src[i];
                *(uint2*)(Ap + i * 8) = make_uint2(h2u(__float22half2_rn(make_float2(v.x, v.y))),
                                                   h2u(__float22half2_rn(make_float2(v.z, v.w))));
            }
        }
        __syncthreads();

        // GEMM 128x256 (K=64): warp tile 16 x 64, 2 col passes
        const uint32_t aB = sb + SM_A + (uint32_t)(16 * mg) * 144u + off144;
        #pragma unroll 1
        for (int p2 = 0; p2 < 2; p2++) {
            float c[32];
            #pragma unroll
            for (int i = 0; i < 32; i++) c[i] = 0.0f;

            const uint32_t wB = sb + SM_W1 + (uint32_t)ng * 18432u
                              + (uint32_t)(64 * p2) * 144u + off144;
            #pragma unroll
            for (int kc = 0; kc < 4; kc++) {
                uint32_t a0, a1, a2, a3;
                LDSM4(a0, a1, a2, a3, aB + kc * 32);
                uint32_t bb[16];
                #pragma unroll
                for (int bi = 0; bi < 4; bi++)
                    LDSM4(bb[4 * bi], bb[4 * bi + 1], bb[4 * bi + 2], bb[4 * bi + 3],
                          wB + (uint32_t)bi * (16u * 144u) + kc * 32);
                #pragma unroll
                for (int bi = 0; bi < 4; bi++) {
                    MMA_F16(c + (2 * bi) * 4,     a0, a1, a2, a3, bb[4 * bi],     bb[4 * bi + 2]);
                    MMA_F16(c + (2 * bi + 1) * 4, a0, a1, a2, a3, bb[4 * bi + 1], bb[4 * bi + 3]);
                }
            }

            // stage (c + b1) fp16 into SM_W2 (528B rows)
            #pragma unroll
            for (int j = 0; j < 8; j++) {
                int col = 128 * ng + 64 * p2 + 8 * j + hCol2;
                float2 bv = *(const float2*)(b1 + col);
                #pragma unroll
                for (int rr = 0; rr < 2; rr++) {
                    int row = 16 * mg + 8 * rr + hRow;
                    *(uint32_t*)(sm + SM_W2 + (size_t)row * 528 + (size_t)col * 2) =
                        h2u(__floats2half2_rn(c[j * 4 + 2 * rr + 0] + bv.x,
                                              c[j * 4 + 2 * rr + 1] + bv.y));
                }
            }
        }
        __syncthreads();

        // coalesced copy to glGB
        for (int i = t; i < 4096; i += 512) {
            int row = i >> 5, w = i & 31;
            *(uint4*)(glGB + (size_t)b * 65536 + (size_t)row * 512 + (size_t)w * 16) =
                *(const uint4*)(sm + SM_W2 + (size_t)row * 528 + (size_t)w * 16);
        }
        __syncthreads();
        if (t == 0) { __threadfence(); atomicExch(&g_gbflag[b], 1); }
    }

    // ================= convert weights into smem (per-CTA) =================
    for (int i = t; i < 16384; i += 512) {               // W1 x-part (k 0..63)
        int k = i >> 8, n = i & 255;
        uint32_t off = (uint32_t)(n >> 7) * 18432u + (uint32_t)(n & 127) * 144u + (uint32_t)k * 2u;
        *(__half*)(sm + SM_W1 + off) = __float2half(W1[k * 256 + n]);
    }
    for (int i = t; i < 32768; i += 512) {               // W2
        int k = i >> 7, n = i & 127;
        uint32_t off = (uint32_t)(k >> 7) * 34816u + (uint32_t)n * 272u + (uint32_t)(k & 127) * 2u;
        *(__half*)(sm + SM_W2 + off) = __float2half(W2[k * 128 + n]);
    }
    if (t < 128) ((float*)(sm + SM_B2))[t] = b2[t];
    __syncthreads();

    // ================= MLP tile loop (R15 structure) =================
    const uint32_t aBase = sb + SM_A + (uint32_t)(16 * mg) * 144u + off144;
    const uint32_t hBase = sb + SM_H + (uint32_t)(16 * mg) * 272u + off272;
    const float* b2s = (const float*)(sm + SM_B2);
    const uint32_t* GB32 = (const uint32_t*)glGB;
    const uint4* xs4 = (const uint4*)x;
    uint4* od4 = (uint4*)out;

    if (t == 0) s_tile[0] = atomicAdd(&g_ticket, 1);
    __syncthreads();
    int tile = s_tile[0];
    int slot = 0;
    if (tile < NTILES_) build_A(sm + SM_A, tile << 7, x, t);
    __syncthreads();

    while (tile < NTILES_) {
        if (t == 0) {
            s_tile[slot ^ 1] = atomicAdd(&g_ticket, 1);
            while (atomicAdd(&g_gbflag[tile & 255], 0) == 0) {}   // GB block ready?
        }
        __syncthreads();
        const int next = s_tile[slot ^ 1];
        const int m0 = tile << 7;
        const int e0 = m0 & (E_ - 1);
        const size_t xb = (size_t)tile * XC_PER_TILE;

        if (next < NTILES_) {
            const char* px = (const char*)(x + ((size_t)(7 * E_) + ((size_t)next << 7)) * 64);
            if (t < 256) PREF_L2(px + (size_t)t * 128);
            const char* pg = (const char*)glGB + (size_t)((next << 7) & (E_ - 1)) * 512;
            PREF_L2(pg + (size_t)t * 128);
        }

        uint4 cr0, cr1;
        XCOPY_ISSUE(0);

        float c2[32];
        #pragma unroll
        for (int i = 0; i < 32; i++) c2[i] = 0.0f;

        #pragma unroll 1
        for (int h = 0; h < 2; h++) {
            // ---- GEMM1 half h: K=64 ----
            float c1[32];
            #pragma unroll
            for (int i = 0; i < 32; i++) c1[i] = 0.0f;

            const uint32_t w1A = sb + SM_W1 + (uint32_t)h * 18432u + (uint32_t)(64 * ng) * 144u + off144;
            #pragma unroll
            for (int kc = 0; kc < 4; kc++) {
                uint32_t a0, a1, a2, a3;
                LDSM4(a0, a1, a2, a3, aBase + kc * 32);
                uint32_t bb[16];
                #pragma unroll
                for (int bi = 0; bi < 4; bi++)
                    LDSM4(bb[4 * bi], bb[4 * bi + 1], bb[4 * bi + 2], bb[4 * bi + 3],
                          w1A + (uint32_t)bi * (16u * 144u) + kc * 32);
                #pragma unroll
                for (int bi = 0; bi < 4; bi++) {
                    MMA_F16(c1 + (2 * bi) * 4,     a0, a1, a2, a3, bb[4 * bi],     bb[4 * bi + 2]);
                    MMA_F16(c1 + (2 * bi + 1) * 4, a0, a1, a2, a3, bb[4 * bi + 1], bb[4 * bi + 3]);
                }
            }

            // GB fragments (L2-prefetched a tile ago)
            uint32_t gbv[16];
            {
                const int cb0 = 64 * h + 32 * ng + (hCol2 >> 1);
                const int rbase = e0 + 16 * mg + hRow;
                #pragma unroll
                for (int j = 0; j < 8; j++) {
                    gbv[2 * j]     = GB32[(size_t)rbase * 128 + cb0 + 4 * j];
                    gbv[2 * j + 1] = GB32[(size_t)(rbase + 8) * 128 + cb0 + 4 * j];
                }
            }

            __syncthreads();

            // ---- convert: relu(c1 + GB) -> fp16 H ----
            #pragma unroll
            for (int j = 0; j < 8; j++) {
                const int colh = 64 * ng + 8 * j + hCol2;
                float2 f0 = __half22float2(*(__half2*)&gbv[2 * j]);
                float2 f1 = __half22float2(*(__half2*)&gbv[2 * j + 1]);
                float v0 = fmaxf(c1[j * 4 + 0] + f0.x, 0.0f);
                float v1 = fmaxf(c1[j * 4 + 1] + f0.y, 0.0f);
                float v2 = fmaxf(c1[j * 4 + 2] + f1.x, 0.0f);
                float v3 = fmaxf(c1[j * 4 + 3] + f1.y, 0.0f);
                unsigned char* hp = sm + SM_H + (size_t)(16 * mg + hRow) * 272 + (size_t)colh * 2;
                *(uint32_t*)hp             = h2u(__float22half2_rn(make_float2(v0, v1)));
                *(uint32_t*)(hp + 8 * 272) = h2u(__float22half2_rn(make_float2(v2, v3)));
            }

            if (h == 0) { XCOPY_CONSUME(0); XCOPY_ISSUE(1); }
            else        { XCOPY_CONSUME(2); XCOPY_ISSUE(3); }

            if (h == 1 && next < NTILES_) build_A(sm + SM_A, next << 7, x, t);

            __syncthreads();

            // ---- GEMM2 half h: K=128 of 256 ----
            const uint32_t w2A = sb + SM_W2 + (uint32_t)h * 34816u + (uint32_t)(64 * ng) * 272u + off272;
            #pragma unroll 1
            for (int kc = 0; kc < 8; kc++) {
                uint32_t a0, a1, a2, a3;
                LDSM4(a0, a1, a2, a3, hBase + kc * 32);
                uint32_t bb[16];
                #pragma unroll
                for (int bi = 0; bi < 4; bi++)
                    LDSM4(bb[4 * bi], bb[4 * bi + 1], bb[4 * bi + 2], bb[4 * bi + 3],
                          w2A + (uint32_t)bi * (16u * 272u) + kc * 32);
                #pragma unroll
                for (int bi = 0; bi < 4; bi++) {
                    MMA_F16(c2 + (2 * bi) * 4,     a0, a1, a2, a3, bb[4 * bi],     bb[4 * bi + 2]);
                    MMA_F16(c2 + (2 * bi + 1) * 4, a0, a1, a2, a3, bb[4 * bi + 1], bb[4 * bi + 3]);
                }
            }

            // ---- P2 (after GEMM2 h0): x-copy rotate + OLD edges (vectorized) ----
            if (h == 0) {
                XCOPY_CONSUME(1);
                XCOPY_ISSUE(2);
                if (t < 272) {
                    int i = tile * OE_PER_TILE + 2 * t;
                    int b = i >> 16, j = i & 65535;
                    int ll = OE_L[b], pp = OE_P[b], dd = OE_D[b];
                    int e0b = E_ * ((1 << (ll - dd)) - 1) + ((pp >> (dd - 1)) << 15);
                    int bt  = E_ * ((1 << ll) - 1) + (pp << 16) + j;
                    int e1i = j & (E_ - 1), e2i = (j + 1) & (E_ - 1);
                    __stcs((float2*)(out + EI_OFF_ + i),
                           make_float2((float)(e0b + e1i), (float)(e0b + e2i)));
                    __stcs((float2*)(out + EI_OFF_ + (size_t)NE_TOT_ + i),
                           make_float2((float)bt, (float)(bt + 1)));
                    __stcs((float2*)(out + EA_OFF_ + i),
                           make_float2((float)dd, (float)dd));
                }
            }
        }

        // ---- epilogue: out = c2 + b2 (streaming stores) ----
        #pragma unroll
        for (int j = 0; j < 8; j++) {
            const int n0 = 64 * ng + 8 * j + hCol2;
            const int f = n0 & 63;
            const float2 bb = *(const float2*)(b2s + n0);
            #pragma unroll
            for (int rr = 0; rr < 2; rr++) {
                const int m = m0 + 16 * mg + 8 * rr + hRow;
                const int p = m >> 15, e = m & (E_ - 1);
                size_t orow = (size_t)N0_ + ((size_t)p << 16) + 2u * (size_t)e + (size_t)ng;
                float2 v;
                v.x = c2[j * 4 + 2 * rr + 0] + bb.x;
                v.y = c2[j * 4 + 2 * rr + 1] + bb.y;
                __stcs((float2*)(out + orow * 64 + f), v);
            }
        }

        // ---- P4: final x-copy consume + NEW edges + events (vectorized) ----
        {
            XCOPY_CONSUME(3);
            {
                int i = tile * NEDGE_PER_TILE + 2 * t;
                int p = i >> 18, rem = i & 262143, dm1 = rem >> 16, j = rem & 65535;
                int e1i = j & (E_ - 1), e2i = (j + 1) & (E_ - 1);
                int sb_ = E_ * ((8 >> dm1) - 1) + ((p >> dm1) << 15);
                int tg  = N0_ + (p << 16) + j;
                __stcs((float2*)(out + EI_OFF_ + NE_OLD_ + i),
                       make_float2((float)(sb_ + e1i), (float)(sb_ + e2i)));
                __stcs((float2*)(out + EI_OFF_ + (size_t)NE_TOT_ + NE_OLD_ + i),
                       make_float2((float)tg, (float)(tg + 1)));
                __stcs((float2*)(out + EA_OFF_ + NE_OLD_ + i),
                       make_float2((float)(dm1 + 1), (float)(dm1 + 1)));
            }
            if (t < 124) {
                int j = tile * EVT_PER_TILE + 4 * t;
                float v0 = (float)(j & (E_ - 1));
                __stcs((float4*)(out + EV_OFF_ + j),
                       make_float4(v0, v0 + 1.0f, v0 + 2.0f, v0 + 3.0f));
            }
        }

        tile = next;
        slot ^= 1;
    }

    // ================= reset coordination state for next replay =================
    __syncthreads();
    if (t == 0) {
        int d = atomicAdd(&g_done, 1);
        if (d == (int)gridDim.x - 1) {
            g_ticket = 0;
            g_gbwork = 0;
            g_done = 0;
            #pragma unroll 8
            for (int i = 0; i < 256; i++) g_gbflag[i] = 0;
            __threadfence();
        }
    }
}

// ---------------- launch ----------------
extern "C" void kernel_launch(void* const* d_in, const int* in_sizes, int n_in,
                              void* d_out, int out_size)
{
    const float* x  = (const float*)d_in[0];
    const float* g  = (const float*)d_in[4];
    const float* W1 = (const float*)d_in[5];
    const float* b1 = (const float*)d_in[6];
    const float* W2 = (const float*)d_in[7];
    const float* b2 = (const float*)d_in[8];
    float* out = (float*)d_out;

    cudaFuncSetAttribute(fused_kernel, cudaFuncAttributeMaxDynamicSharedMemorySize, SM_SZ);
    fused_kernel<<<152, 512, SM_SZ>>>(x, g, W1, b1, W2, b2, out);
}

// round 17
// speedup vs baseline: 1.0618x; 1.0618x over previous
#include <cuda_runtime.h>
#include <cuda_fp16.h>
#include <cstdint>

// ---------------- problem constants ----------------
#define E_      32768
#define N0_     (15 * E_)
#define NTILES_ 2048                  // 262144 MLP rows / 128
#define NE_OLD_ 1114112
#define NE_NEW_ 2097152
#define NE_TOT_ (NE_OLD_ + NE_NEW_)
#define NNODES_ (31 * E_)

#define EI_OFF_ ((size_t)NNODES_ * 64)
#define EA_OFF_ (EI_OFF_ + 2ull * NE_TOT_)
#define EV_OFF_ (EA_OFF_ + (size_t)NE_TOT_)

// per-tile aux chunks (exact divisions by 2048)
#define XC_PER_TILE 3840              // uint4 of x-copy per MLP tile
#define OE_PER_TILE 544               // old edges per tile
#define NEDGE_PER_TILE 1024           // new edges per tile
#define EVT_PER_TILE 496              // events per tile

// old-edge block tables: block b (= i>>16, b<17) -> (l, p, d)
__device__ __constant__ unsigned char OE_L[17] = {1, 2,2,2,2, 3,3,3,3,3,3,3,3,3,3,3,3};
__device__ __constant__ unsigned char OE_P[17] = {0, 0,0,1,1, 0,0,0,1,1,1,2,2,2,3,3,3};
__device__ __constant__ unsigned char OE_D[17] = {1, 1,2,1,2, 1,2,3,1,2,3,1,2,3,1,2,3};

// ---------------- PTX helpers (base ISA only) ----------------
__device__ __forceinline__ uint32_t smem_u32(const void* p) {
    uint32_t a;
    asm("{ .reg .u64 t; cvta.to.shared.u64 t, %1; cvt.u32.u64 %0, t; }" : "=r"(a) : "l"(p));
    return a;
}

#define CPA16(dst, src) asm volatile("cp.async.cg.shared.global [%0], [%1], 16;" :: "r"(dst), "l"(src) : "memory")
#define CPA_COMMIT()    asm volatile("cp.async.commit_group;" ::: "memory")
#define CPA_WAIT(n)     asm volatile("cp.async.wait_group %0;" :: "n"(n) : "memory")
#define PREF_L2(p)      asm volatile("prefetch.global.L2 [%0];" :: "l"(p))

#define LDSM4(r0, r1, r2, r3, a)                                                   \
    asm volatile("ldmatrix.sync.aligned.m8n8.x4.shared.b16 {%0,%1,%2,%3}, [%4];"   \
        : "=r"(r0), "=r"(r1), "=r"(r2), "=r"(r3) : "r"(a))

#define MMA_F16(d, a0, a1, a2, a3, b0, b1)                                         \
    asm volatile("mma.sync.aligned.m16n8k16.row.col.f32.f16.f16.f32 "              \
        "{%0,%1,%2,%3}, {%4,%5,%6,%7}, {%8,%9}, {%0,%1,%2,%3};"                    \
        : "+f"((d)[0]), "+f"((d)[1]), "+f"((d)[2]), "+f"((d)[3])                   \
        : "r"(a0), "r"(a1), "r"(a2), "r"(a3), "r"(b0), "r"(b1))

__device__ __forceinline__ uint32_t h2u(__half2 h) {
    return *reinterpret_cast<uint32_t*>(&h);
}

// ---------------- device scratch ----------------
__device__ __align__(16) unsigned char glW1[36864];        // [h][128n][144B], k 0..63
__device__ __align__(16) unsigned char glW2[2 * 34816];    // [kh][128n][272B]
__device__ __align__(16) unsigned char glGB[(size_t)E_ * 512];  // GB = G@W1bot + b1
__device__ int g_ticket;

// ============================================================================
// gbprep: GB GEMM (2 blocks/CTA) + weight images + ticket reset
// ============================================================================
#define GBP_SM_A   0
#define GBP_SM_W   18432
#define GBP_SM_OUT 55296
#define GBP_SM_SZ  (55296 + 67584)

__global__ void __launch_bounds__(512, 1)
gbprep_kernel(const float* __restrict__ g, const float* __restrict__ W1,
              const float* __restrict__ W2, const float* __restrict__ b1)
{
    extern __shared__ __align__(128) unsigned char sm[];
    const int t = threadIdx.x, cb = blockIdx.x;   // grid = 128
    const int wid = t >> 5, l = t & 31;
    const uint32_t sb = smem_u32(sm);

    if (cb == 0 && t == 0) g_ticket = 0;

    // weight images for the MLP kernel
    if (cb < 32) {
        int i = cb * 512 + t;                 // W1 x-part (k 0..63)
        int k = i >> 8, n = i & 255;
        uint32_t off = (uint32_t)(n >> 7) * 18432u + (uint32_t)(n & 127) * 144u + (uint32_t)k * 2u;
        *(__half*)(glW1 + off) = __float2half(W1[k * 256 + n]);
    } else if (cb < 96) {
        int i = (cb - 32) * 512 + t;          // W2
        int k = i >> 7, n = i & 127;
        uint32_t off = (uint32_t)(k >> 7) * 34816u + (uint32_t)n * 272u + (uint32_t)(k & 127) * 2u;
        *(__half*)(glW2 + off) = __float2half(W2[k * 128 + n]);
    }

    // W1 bottom (k 64..127) -> smem [nh][128n][144B]  (amortized over 2 blocks)
    for (int i = t; i < 16384; i += 512) {
        int kk = i >> 8, n = i & 255;
        uint32_t off = (uint32_t)(n >> 7) * 18432u + (uint32_t)(n & 127) * 144u + (uint32_t)kk * 2u;
        *(__half*)(sm + GBP_SM_W + off) = __float2half(W1[(64 + kk) * 256 + n]);
    }

    const int mg = wid & 7, ng = wid >> 3;
    const uint32_t off144 = (uint32_t)(l & 15) * 144u + (uint32_t)((l >> 4) << 4);
    const uint32_t aB = sb + GBP_SM_A + (uint32_t)(16 * mg) * 144u + off144;
    const uint32_t wB = sb + GBP_SM_W + (uint32_t)ng * 18432u + off144;
    const int hRow = l >> 2, hCol2 = (l & 3) << 1;

    #pragma unroll 1
    for (int bk = 0; bk < 2; bk++) {
        const int blk = cb * 2 + bk;          // 0..255

        // g tile rows [128*blk, +128)
        {
            const int r = t >> 2, q = t & 3;
            const float4* src = (const float4*)(g + ((size_t)(blk * 128 + r)) * 64 + 16 * q);
            unsigned char* Ap = sm + GBP_SM_A + (size_t)r * 144 + (size_t)q * 32;
            #pragma unroll
            for (int i = 0; i < 4; i++) {
                float4 v = src[i];
                *(uint2*)(Ap + i * 8) = make_uint2(h2u(__float22half2_rn(make_float2(v.x, v.y))),
                                                   h2u(__float22half2_rn(make_float2(v.z, v.w))));
            }
        }
        __syncthreads();

        float c[64];
        #pragma unroll
        for (int i = 0; i < 64; i++) c[i] = 0.0f;

        #pragma unroll
        for (int kc = 0; kc < 4; kc++) {
            uint32_t a0, a1, a2, a3;
            LDSM4(a0, a1, a2, a3, aB + kc * 32);
            #pragma unroll
            for (int hf = 0; hf < 2; hf++) {
                uint32_t bb[16];
                #pragma unroll
                for (int b2 = 0; b2 < 4; b2++)
                    LDSM4(bb[4 * b2], bb[4 * b2 + 1], bb[4 * b2 + 2], bb[4 * b2 + 3],
                          wB + (uint32_t)(4 * hf + b2) * (16u * 144u) + kc * 32);
                #pragma unroll
                for (int b2 = 0; b2 < 4; b2++) {
                    int j0 = 2 * (4 * hf + b2);
                    MMA_F16(c + j0 * 4,       a0, a1, a2, a3, bb[4 * b2],     bb[4 * b2 + 2]);
                    MMA_F16(c + (j0 + 1) * 4, a0, a1, a2, a3, bb[4 * b2 + 1], bb[4 * b2 + 3]);
                }
            }
        }

        // stage (c + b1) fp16 into padded smem, then coalesced store
        #pragma unroll
        for (int j = 0; j < 16; j++) {
            int col = 128 * ng + 8 * j + hCol2;
            float2 bv = *(const float2*)(b1 + col);
            #pragma unroll
            for (int rr = 0; rr < 2; rr++) {
                int row = 16 * mg + 8 * rr + hRow;
                *(uint32_t*)(sm + GBP_SM_OUT + (size_t)row * 528 + (size_t)col * 2) =
                    h2u(__floats2half2_rn(c[j * 4 + 2 * rr + 0] + bv.x,
                                          c[j * 4 + 2 * rr + 1] + bv.y));
            }
        }
        __syncthreads();
        for (int i = t; i < 4096; i += 512) {
            int row = i >> 5, w = i & 31;
            *(uint4*)(glGB + (size_t)blk * 65536 + (size_t)row * 512 + (size_t)w * 16) =
                *(const uint4*)(sm + GBP_SM_OUT + (size_t)row * 528 + (size_t)w * 16);
        }
        if (bk == 0) __syncthreads();         // OUT/A reuse safe for block 2
    }
}

// ============================================================================
// persistent MLP: R15 structure + vectorized analytic fills
// ============================================================================
#define SM_A    0                         // 18432
#define SM_W1   18432                     // 36864
#define SM_W2   55296                     // 69632
#define SM_H    124928                    // 34816
#define SM_B2   159744                    // 512
#define SM_SZ   160256

__device__ __forceinline__ void build_A(unsigned char* Abuf, int m0,
                                        const float* __restrict__ x, int t)
{
    const int r = t >> 2, q = t & 3;
    const float4* src = (const float4*)(x + ((size_t)(7 * E_) + (size_t)(m0 + r)) * 64 + 16 * q);
    unsigned char* Ap = Abuf + (size_t)r * 144 + (size_t)q * 32;
    #pragma unroll
    for (int i = 0; i < 4; i++) {
        float4 v = src[i];
        *(uint2*)(Ap + i * 8) = make_uint2(h2u(__float22half2_rn(make_float2(v.x, v.y))),
                                           h2u(__float22half2_rn(make_float2(v.z, v.w))));
    }
}

#define XCOPY_ISSUE(k)                                                              \
    do {                                                                            \
        int _i0 = t + (2 * (k)) * 512, _i1 = t + (2 * (k) + 1) * 512;               \
        if (_i0 < XC_PER_TILE) cr0 = __ldcs(xs4 + xb + _i0);                        \
        if (_i1 < XC_PER_TILE) cr1 = __ldcs(xs4 + xb + _i1);                        \
    } while (0)

#define XCOPY_CONSUME(k)                                                            \
    do {                                                                            \
        int _i0 = t + (2 * (k)) * 512, _i1 = t + (2 * (k) + 1) * 512;               \
        if (_i0 < XC_PER_TILE) __stcs(od4 + xb + _i0, cr0);                         \
        if (_i1 < XC_PER_TILE) __stcs(od4 + xb + _i1, cr1);                         \
    } while (0)

__global__ void __launch_bounds__(512, 1)
mlp_mma_kernel(const float* __restrict__ x,
               const float* __restrict__ b2,
               float* __restrict__ out)
{
    extern __shared__ __align__(128) unsigned char sm[];
    __shared__ int s_tile[2];

    const int t = threadIdx.x;
    const int wid = t >> 5, l = t & 31;
    const int mg = wid & 7;
    const int ng = wid >> 3;
    const uint32_t sb = smem_u32(sm);

    for (int i = t; i < 2304; i += 512) CPA16(sb + SM_W1 + (uint32_t)i * 16, glW1 + (size_t)i * 16);
    for (int i = t; i < 4352; i += 512) CPA16(sb + SM_W2 + (uint32_t)i * 16, glW2 + (size_t)i * 16);
    CPA_COMMIT();

    if (t < 128) ((float*)(sm + SM_B2))[t] = b2[t];

    const uint32_t off144 = (uint32_t)(l & 15) * 144u + (uint32_t)((l >> 4) << 4);
    const uint32_t off272 = (uint32_t)(l & 15) * 272u + (uint32_t)((l >> 4) << 4);
    const uint32_t aBase = sb + SM_A + (uint32_t)(16 * mg) * 144u + off144;
    const uint32_t hBase = sb + SM_H + (uint32_t)(16 * mg) * 272u + off272;
    const float* b2s = (const float*)(sm + SM_B2);
    const uint32_t* GB32 = (const uint32_t*)glGB;
    const uint4* xs4 = (const uint4*)x;
    uint4* od4 = (uint4*)out;

    const int hRow = l >> 2;
    const int hCol2 = (l & 3) << 1;

    // prologue
    if (t == 0) s_tile[0] = atomicAdd(&g_ticket, 1);
    __syncthreads();
    int tile = s_tile[0];
    int slot = 0;
    if (tile < NTILES_) build_A(sm + SM_A, tile << 7, x, t);
    CPA_WAIT(0);                       // weights resident
    __syncthreads();

    while (tile < NTILES_) {
        if (t == 0) s_tile[slot ^ 1] = atomicAdd(&g_ticket, 1);
        __syncthreads();
        const int next = s_tile[slot ^ 1];
        const int m0 = tile << 7;
        const int e0 = m0 & (E_ - 1);
        const size_t xb = (size_t)tile * XC_PER_TILE;

        if (next < NTILES_) {
            const char* px = (const char*)(x + ((size_t)(7 * E_) + ((size_t)next << 7)) * 64);
            if (t < 256) PREF_L2(px + (size_t)t * 128);
            const char* pg = (const char*)glGB + (size_t)((next << 7) & (E_ - 1)) * 512;
            PREF_L2(pg + (size_t)t * 128);
        }

        // ---- x-copy P0 issue ----
        uint4 cr0, cr1;
        XCOPY_ISSUE(0);

        float c2[32];
        #pragma unroll
        for (int i = 0; i < 32; i++) c2[i] = 0.0f;

        #pragma unroll 1
        for (int h = 0; h < 2; h++) {
            // ---- GEMM1 half h: K=64 ----
            float c1[32];
            #pragma unroll
            for (int i = 0; i < 32; i++) c1[i] = 0.0f;

            const uint32_t w1A = sb + SM_W1 + (uint32_t)h * 18432u + (uint32_t)(64 * ng) * 144u + off144;
            #pragma unroll
            for (int kc = 0; kc < 4; kc++) {
                uint32_t a0, a1, a2, a3;
                LDSM4(a0, a1, a2, a3, aBase + kc * 32);
                uint32_t bb[16];
                #pragma unroll
                for (int bi = 0; bi < 4; bi++)
                    LDSM4(bb[4 * bi], bb[4 * bi + 1], bb[4 * bi + 2], bb[4 * bi + 3],
                          w1A + (uint32_t)bi * (16u * 144u) + kc * 32);
                #pragma unroll
                for (int bi = 0; bi < 4; bi++) {
                    MMA_F16(c1 + (2 * bi) * 4,     a0, a1, a2, a3, bb[4 * bi],     bb[4 * bi + 2]);
                    MMA_F16(c1 + (2 * bi + 1) * 4, a0, a1, a2, a3, bb[4 * bi + 1], bb[4 * bi + 3]);
                }
            }

            // GB fragments (L2-prefetched a tile ago)
            uint32_t gbv[16];
            {
                const int cb0 = 64 * h + 32 * ng + (hCol2 >> 1);
                const int rbase = e0 + 16 * mg + hRow;
                #pragma unroll
                for (int j = 0; j < 8; j++) {
                    gbv[2 * j]     = GB32[(size_t)rbase * 128 + cb0 + 4 * j];
                    gbv[2 * j + 1] = GB32[(size_t)(rbase + 8) * 128 + cb0 + 4 * j];
                }
            }

            __syncthreads();

            // ---- convert: relu(c1 + GB) -> fp16 H ----
            #pragma unroll
            for (int j = 0; j < 8; j++) {
                const int colh = 64 * ng + 8 * j + hCol2;
                float2 f0 = __half22float2(*(__half2*)&gbv[2 * j]);
                float2 f1 = __half22float2(*(__half2*)&gbv[2 * j + 1]);
                float v0 = fmaxf(c1[j * 4 + 0] + f0.x, 0.0f);
                float v1 = fmaxf(c1[j * 4 + 1] + f0.y, 0.0f);
                float v2 = fmaxf(c1[j * 4 + 2] + f1.x, 0.0f);
                float v3 = fmaxf(c1[j * 4 + 3] + f1.y, 0.0f);
                unsigned char* hp = sm + SM_H + (size_t)(16 * mg + hRow) * 272 + (size_t)colh * 2;
                *(uint32_t*)hp             = h2u(__float22half2_rn(make_float2(v0, v1)));
                *(uint32_t*)(hp + 8 * 272) = h2u(__float22half2_rn(make_float2(v2, v3)));
            }

            // x-copy: P1 (h=0) consume0 issue1; P3 (h=1) consume2 issue3
            if (h == 0) { XCOPY_CONSUME(0); XCOPY_ISSUE(1); }
            else        { XCOPY_CONSUME(2); XCOPY_ISSUE(3); }

            if (h == 1 && next < NTILES_) build_A(sm + SM_A, next << 7, x, t);

            __syncthreads();

            // ---- GEMM2 half h: K=128 of 256 ----
            const uint32_t w2A = sb + SM_W2 + (uint32_t)h * 34816u + (uint32_t)(64 * ng) * 272u + off272;
            #pragma unroll 1
            for (int kc = 0; kc < 8; kc++) {
                uint32_t a0, a1, a2, a3;
                LDSM4(a0, a1, a2, a3, hBase + kc * 32);
                uint32_t bb[16];
                #pragma unroll
                for (int bi = 0; bi < 4; bi++)
                    LDSM4(bb[4 * bi], bb[4 * bi + 1], bb[4 * bi + 2], bb[4 * bi + 3],
                          w2A + (uint32_t)bi * (16u * 272u) + kc * 32);
                #pragma unroll
                for (int bi = 0; bi < 4; bi++) {
                    MMA_F16(c2 + (2 * bi) * 4,     a0, a1, a2, a3, bb[4 * bi],     bb[4 * bi + 2]);
                    MMA_F16(c2 + (2 * bi + 1) * 4, a0, a1, a2, a3, bb[4 * bi + 1], bb[4 * bi + 3]);
                }
            }

            // ---- P2 (after GEMM2 h0): x-copy rotate + OLD edges (vectorized) ----
            if (h == 0) {
                XCOPY_CONSUME(1);
                XCOPY_ISSUE(2);
                if (t < 272) {
                    int i = tile * OE_PER_TILE + 2 * t;     // even; within one block
                    int b = i >> 16, j = i & 65535;
                    int ll = OE_L[b], pp = OE_P[b], dd = OE_D[b];
                    int e0b = E_ * ((1 << (ll - dd)) - 1) + ((pp >> (dd - 1)) << 15);
                    int bt  = E_ * ((1 << ll) - 1) + (pp << 16) + j;
                    int e1i = j & (E_ - 1), e2i = (j + 1) & (E_ - 1);
                    __stcs((float2*)(out + EI_OFF_ + i),
                           make_float2((float)(e0b + e1i), (float)(e0b + e2i)));
                    __stcs((float2*)(out + EI_OFF_ + (size_t)NE_TOT_ + i),
                           make_float2((float)bt, (float)(bt + 1)));
                    __stcs((float2*)(out + EA_OFF_ + i),
                           make_float2((float)dd, (float)dd));
                }
            }
        }

        // ---- epilogue: out = c2 + b2 (streaming stores) ----
        #pragma unroll
        for (int j = 0; j < 8; j++) {
            const int n0 = 64 * ng + 8 * j + hCol2;
            const int f = n0 & 63;
            const float2 bb = *(const float2*)(b2s + n0);
            #pragma unroll
            for (int rr = 0; rr < 2; rr++) {
                const int m = m0 + 16 * mg + 8 * rr + hRow;
                const int p = m >> 15, e = m & (E_ - 1);
                size_t orow = (size_t)N0_ + ((size_t)p << 16) + 2u * (size_t)e + (size_t)ng;
                float2 v;
                v.x = c2[j * 4 + 2 * rr + 0] + bb.x;
                v.y = c2[j * 4 + 2 * rr + 1] + bb.y;
                __stcs((float2*)(out + orow * 64 + f), v);
            }
        }

        // ---- P4: final x-copy consume + NEW edges + events (vectorized) ----
        {
            XCOPY_CONSUME(3);
            {
                int i = tile * NEDGE_PER_TILE + 2 * t;      // even; within one (p,d) block
                int p = i >> 18, rem = i & 262143, dm1 = rem >> 16, j = rem & 65535;
                int e1i = j & (E_ - 1), e2i = (j + 1) & (E_ - 1);
                int sb_ = E_ * ((8 >> dm1) - 1) + ((p >> dm1) << 15);
                int tg  = N0_ + (p << 16) + j;
                __stcs((float2*)(out + EI_OFF_ + NE_OLD_ + i),
                       make_float2((float)(sb_ + e1i), (float)(sb_ + e2i)));
                __stcs((float2*)(out + EI_OFF_ + (size_t)NE_TOT_ + NE_OLD_ + i),
                       make_float2((float)tg, (float)(tg + 1)));
                __stcs((float2*)(out + EA_OFF_ + NE_OLD_ + i),
                       make_float2((float)(dm1 + 1), (float)(dm1 + 1)));
            }
            if (t < 124) {
                int j = tile * EVT_PER_TILE + 4 * t;        // 496 = 124*4; j mod E never wraps mid-4
                float v0 = (float)(j & (E_ - 1));
                __stcs((float4*)(out + EV_OFF_ + j),
                       make_float4(v0, v0 + 1.0f, v0 + 2.0f, v0 + 3.0f));
            }
        }

        tile = next;
        slot ^= 1;
    }
}

// ---------------- launch ----------------
extern "C" void kernel_launch(void* const* d_in, const int* in_sizes, int n_in,
                              void* d_out, int out_size)
{
    const float* x  = (const float*)d_in[0];
    const float* g  = (const float*)d_in[4];
    const float* W1 = (const float*)d_in[5];
    const float* b1 = (const float*)d_in[6];
    const float* W2 = (const float*)d_in[7];
    const float* b2 = (const float*)d_in[8];
    float* out = (float*)d_out;

    cudaFuncSetAttribute(gbprep_kernel, cudaFuncAttributeMaxDynamicSharedMemorySize, GBP_SM_SZ);
    gbprep_kernel<<<128, 512, GBP_SM_SZ>>>(g, W1, W2, b1);

    cudaFuncSetAttribute(mlp_mma_kernel, cudaFuncAttributeMaxDynamicSharedMemorySize, SM_SZ);
    mlp_mma_kernel<<<152, 512, SM_SZ>>>(x, b2, out);
}